// round 2
// baseline (speedup 1.0000x reference)
#include <cuda_runtime.h>

// out[b,s,c] = dequant(quant(x[b,s,c])) where channel c's group (of 128) is
// determined by its position inv[c] in the permuted order. The two takes
// cancel on the value path; only group membership is permuted.
//
// One block per row of 4096 floats. All global traffic is 128-bit and
// coalesced; the permutation is resolved entirely in shared memory.

#define ROW_C     4096
#define NTHREADS  1024
#define Q_MAX     15.0f
#define EPS       1e-5f

__global__ __launch_bounds__(NTHREADS, 2)
void tpq_kernel(const float4* __restrict__ x4,
                const int*    __restrict__ perm,
                const int4*   __restrict__ inv4,
                float4*       __restrict__ out4)
{
    __shared__ float sx[ROW_C];
    __shared__ float sq[ROW_C];

    const int    tid   = threadIdx.x;
    const size_t base4 = (size_t)blockIdx.x * (ROW_C / 4);

    // ---- coalesced 128-bit row load into smem ----
    {
        const float4 a = x4[base4 + tid];
        sx[4 * tid + 0] = a.x;
        sx[4 * tid + 1] = a.y;
        sx[4 * tid + 2] = a.z;
        sx[4 * tid + 3] = a.w;
    }
    __syncthreads();

    // ---- one warp per group of 128 (32 warps = 32 groups) ----
    const int warp = tid >> 5;
    const int lane = tid & 31;
    const int j0   = warp * 128;

    float v[4];
    int   jj[4];
    float vmin =  INFINITY;
    float vmax = -INFINITY;

    #pragma unroll
    for (int i = 0; i < 4; ++i) {
        const int j = j0 + lane + 32 * i;     // position in permuted order
        jj[i] = j;
        const int p = __ldg(&perm[j]);        // coalesced idx read (L2-resident)
        const float val = sx[p];              // random smem gather (cheap)
        v[i] = val;
        vmin = fminf(vmin, val);
        vmax = fmaxf(vmax, val);
    }

    // warp-wide min/max butterfly
    #pragma unroll
    for (int off = 16; off; off >>= 1) {
        vmin = fminf(vmin, __shfl_xor_sync(0xffffffffu, vmin, off));
        vmax = fmaxf(vmax, __shfl_xor_sync(0xffffffffu, vmax, off));
    }

    // scales = clip(max-min, EPS) / 15 ; base = clip(round(-min/scale), 0, 15)
    const float scale  = fmaxf(vmax - vmin, EPS) / Q_MAX;
    const float base_q = fminf(fmaxf(rintf(-vmin / scale), 0.0f), Q_MAX);

    #pragma unroll
    for (int i = 0; i < 4; ++i) {
        float q = rintf(v[i] / scale) + base_q;
        q = fminf(fmaxf(q, 0.0f), Q_MAX);
        sq[jj[i]] = (q - base_q) * scale;
    }
    __syncthreads();

    // ---- coalesced 128-bit store: out[c] = sq[inv[c]] ----
    {
        const int4 p = __ldg(&inv4[tid]);     // L2-resident index read
        float4 o;
        o.x = sq[p.x];
        o.y = sq[p.y];
        o.z = sq[p.z];
        o.w = sq[p.w];
        out4[base4 + tid] = o;
    }
}

extern "C" void kernel_launch(void* const* d_in, const int* in_sizes, int n_in,
                              void* d_out, int out_size)
{
    const float4* x4   = (const float4*)d_in[0];
    const int*    perm = (const int*)d_in[1];
    const int4*   inv4 = (const int4*)d_in[2];
    float4*       out4 = (float4*)d_out;

    const int rows = in_sizes[0] / ROW_C;   // B*S = 16384
    tpq_kernel<<<rows, NTHREADS>>>(x4, perm, inv4, out4);
}

// round 3
// speedup vs baseline: 1.0530x; 1.0530x over previous
#include <cuda_runtime.h>

// out[c] = dequant(quant(x[c])) where channel c's quant group is inv[c]>>7.
// The permutation take-pair cancels on the value path; only group membership
// is permuted. One block per row of 4096 floats.
//
// Pass A: coalesced float4 load -> registers + smem; warp-per-group random
//         smem gather (by perm) ONLY to reduce min/max; 32-entry param table.
// Pass B: quantize register-held values with table params (group = inv[c]>>7),
//         coalesced float4 store. No second permutation round-trip in smem.

#define ROW_C     4096
#define NTHREADS  1024
#define Q_MAX     15.0f
#define EPS       1e-5f

struct GParam { float inv_scale, scale, base; };

__global__ __launch_bounds__(NTHREADS, 2)
void tpq_kernel(const float4* __restrict__ x4,
                const int*    __restrict__ perm,
                const int4*   __restrict__ inv4,
                float4*       __restrict__ out4)
{
    __shared__ float  sx[ROW_C];
    __shared__ GParam sp[32];

    const int    tid   = threadIdx.x;
    const size_t base4 = (size_t)blockIdx.x * (ROW_C / 4);

    // ---- coalesced 128-bit row load; keep in registers AND smem ----
    const float4 a = x4[base4 + tid];
    // kick off the (L2-resident) index load early; needed only in pass B
    const int4 pinv = __ldg(&inv4[tid]);

    sx[4 * tid + 0] = a.x;
    sx[4 * tid + 1] = a.y;
    sx[4 * tid + 2] = a.z;
    sx[4 * tid + 3] = a.w;
    __syncthreads();

    // ---- pass A: warp w reduces min/max of permuted group w ----
    const int warp = tid >> 5;
    const int lane = tid & 31;
    const int j0   = warp * 128;

    float vmin =  INFINITY;
    float vmax = -INFINITY;

    #pragma unroll
    for (int i = 0; i < 4; ++i) {
        const int p = __ldg(&perm[j0 + lane + 32 * i]);  // coalesced, L2-resident
        const float val = sx[p];                          // random smem gather
        vmin = fminf(vmin, val);
        vmax = fmaxf(vmax, val);
    }

    #pragma unroll
    for (int off = 16; off; off >>= 1) {
        vmin = fminf(vmin, __shfl_xor_sync(0xffffffffu, vmin, off));
        vmax = fmaxf(vmax, __shfl_xor_sync(0xffffffffu, vmax, off));
    }

    if (lane == 0) {
        // scale = clip(max-min, EPS)/15 ; base = clip(round(-min/scale), 0, 15)
        const float scale  = fmaxf(vmax - vmin, EPS) / Q_MAX;
        const float base_q = fminf(fmaxf(rintf(-vmin / scale), 0.0f), Q_MAX);
        GParam g;
        g.inv_scale = 1.0f / scale;
        g.scale     = scale;
        g.base      = base_q;
        sp[warp] = g;
    }
    __syncthreads();

    // ---- pass B: quantize register values; group id = inv[c] >> 7 ----
    float4 o;
    {
        const GParam g = sp[pinv.x >> 7];
        float q = fminf(fmaxf(rintf(a.x * g.inv_scale) + g.base, 0.0f), Q_MAX);
        o.x = (q - g.base) * g.scale;
    }
    {
        const GParam g = sp[pinv.y >> 7];
        float q = fminf(fmaxf(rintf(a.y * g.inv_scale) + g.base, 0.0f), Q_MAX);
        o.y = (q - g.base) * g.scale;
    }
    {
        const GParam g = sp[pinv.z >> 7];
        float q = fminf(fmaxf(rintf(a.z * g.inv_scale) + g.base, 0.0f), Q_MAX);
        o.z = (q - g.base) * g.scale;
    }
    {
        const GParam g = sp[pinv.w >> 7];
        float q = fminf(fmaxf(rintf(a.w * g.inv_scale) + g.base, 0.0f), Q_MAX);
        o.w = (q - g.base) * g.scale;
    }
    out4[base4 + tid] = o;
}

extern "C" void kernel_launch(void* const* d_in, const int* in_sizes, int n_in,
                              void* d_out, int out_size)
{
    const float4* x4   = (const float4*)d_in[0];
    const int*    perm = (const int*)d_in[1];
    const int4*   inv4 = (const int4*)d_in[2];
    float4*       out4 = (float4*)d_out;

    const int rows = in_sizes[0] / ROW_C;   // B*S = 16384
    tpq_kernel<<<rows, NTHREADS>>>(x4, perm, inv4, out4);
}